// round 13
// baseline (speedup 1.0000x reference)
#include <cuda_runtime.h>
#include <cstdint>

// Problem constants (shapes fixed by the dataset)
#define SQ 50          // qubits
#define SP 3           // pauli basis
#define SS 64          // heads
#define WORDS 256      // words per block
#define THREADS 512    // 16 warps; warp quads split 64 heads, 2 words/thread
#define TROW 156       // padded row stride (28i mod 32: 8-lane LDS.128 phases disjoint)

// Packed heads: ha[q][j(32)][4] = {h0s0,h0s1,h1s0,h1s1}
//               hcp[q][jp(16)][4] = {h2(2jp)s0,h2(2jp)s1, h2(2jp+1)s0,h2(2jp+1)s1}
#define HA_TOTAL (SQ * 128)   // 6400
#define HCP_TOTAL (SQ * 64)   // 3200

// smem float offsets
#define OFF_HCP  HA_TOTAL               // 6400
#define OFF_HR   (OFF_HCP + HCP_TOTAL)  // 9600
#define OFF_PART (OFF_HR + SS)          // 9664 (3*256 = 768)
#define OFF_P2   (OFF_PART + 3*WORDS)   // 10432 (2*256 = 512)
#define OFF_RED  (OFF_P2 + 2*WORDS)     // 10944 (16 floats = 8 doubles)
#define OFF_T    (OFF_RED + 16)         // 10960 (43840 B, 16B aligned)
#define SMEM_FLOATS (OFF_T + WORDS * TROW)   // 50896 floats = 203584 B

__device__ double       g_accum;
__device__ unsigned int g_count;
__device__ float        g_ha[HA_TOTAL];
__device__ float        g_hcp[HCP_TOTAL];
__device__ float        g_hr[SS];

__device__ __forceinline__ float softplus20(float x) {
    float y = x * 20.0f;
    return fmaxf(y, 0.0f) + log1pf(expf(-fabsf(y)));
}

// ---------------------------------------------------------------------------
__global__ void prep_kernel(const float* __restrict__ heads_param,
                            const float* __restrict__ hr_param) {
    const int tid = threadIdx.x;

    if (blockIdx.x == 0 && tid == 0) { g_accum = 0.0; g_count = 0u; }

    __shared__ float s_hr[SS];
    if (tid < SS) s_hr[tid] = softplus20(hr_param[tid]);
    __syncthreads();
    if (blockIdx.x == 0 && tid < SS) {
        float s = 0.0f;
        #pragma unroll
        for (int i = 0; i < SS; i++) s += s_hr[i];
        s = fmaxf(s, 1e-12f);
        g_hr[tid] = (s_hr[tid] / s + 0.001f / (float)SS) / 1.001f;
    }

    const int stride = blockDim.x * gridDim.x;
    for (int i = blockIdx.x * blockDim.x + tid; i < SS * SQ; i += stride) {
        int s = i / SQ;
        int q = i - s * SQ;
        const float* hp = heads_param + (s * SQ + q) * SP;
        float h0 = softplus20(hp[0]);
        float h1 = softplus20(hp[1]);
        float h2 = softplus20(hp[2]);
        float inv = 1.0f / fmaxf(h0 + h1 + h2, 1e-12f);
        h0 *= inv; h1 *= inv; h2 *= inv;
        int j = s >> 1, o = s & 1;
        int jp = j >> 1, jo = j & 1;
        g_ha[q * 128 + j * 4 + 0 + o]       = h0;
        g_ha[q * 128 + j * 4 + 2 + o]       = h1;
        g_hcp[q * 64 + jp * 4 + jo * 2 + o] = h2;
    }
}

// ---------------------------------------------------------------------------
// Per-q step: 2 words x 8 head-pairs on precomputed r values.
// inner = h2 + h0*r0 + h1*r1 (all nonneg)
// ---------------------------------------------------------------------------
__device__ __forceinline__ void proc_q2(
    float r0a, float r1a,                // word A
    float r0b, float r1b,                // word B
    const ulonglong2* __restrict__ ha,   // this q, quarter offset: 8 entries
    const ulonglong2* __restrict__ hcp,  // this q, quarter offset: 4 entries
    uint64_t* __restrict__ accA, uint64_t* __restrict__ accB)
{
    uint64_t R0A, R1A, R0B, R1B;
    asm("mov.b64 %0, {%1, %1};" : "=l"(R0A) : "f"(r0a));
    asm("mov.b64 %0, {%1, %1};" : "=l"(R1A) : "f"(r1a));
    asm("mov.b64 %0, {%1, %1};" : "=l"(R0B) : "f"(r0b));
    asm("mov.b64 %0, {%1, %1};" : "=l"(R1B) : "f"(r1b));

    #pragma unroll
    for (int jp = 0; jp < 4; jp++) {
        ulonglong2 HcP = hcp[jp];          // {h2(2jp) pair, h2(2jp+1) pair}
        ulonglong2 Ha0 = ha[2 * jp];
        ulonglong2 Ha1 = ha[2 * jp + 1];
        uint64_t dA, dB;
        // j = 2jp
        asm("fma.rn.f32x2 %0, %1, %2, %3;" : "=l"(dA) : "l"(Ha0.x), "l"(R0A), "l"(HcP.x));
        asm("fma.rn.f32x2 %0, %1, %2, %3;" : "=l"(dB) : "l"(Ha0.x), "l"(R0B), "l"(HcP.x));
        asm("fma.rn.f32x2 %0, %1, %2, %3;" : "=l"(dA) : "l"(Ha0.y), "l"(R1A), "l"(dA));
        asm("fma.rn.f32x2 %0, %1, %2, %3;" : "=l"(dB) : "l"(Ha0.y), "l"(R1B), "l"(dB));
        asm("mul.rn.f32x2 %0, %1, %2;" : "=l"(accA[2*jp]) : "l"(accA[2*jp]), "l"(dA));
        asm("mul.rn.f32x2 %0, %1, %2;" : "=l"(accB[2*jp]) : "l"(accB[2*jp]), "l"(dB));
        // j = 2jp+1
        asm("fma.rn.f32x2 %0, %1, %2, %3;" : "=l"(dA) : "l"(Ha1.x), "l"(R0A), "l"(HcP.y));
        asm("fma.rn.f32x2 %0, %1, %2, %3;" : "=l"(dB) : "l"(Ha1.x), "l"(R0B), "l"(HcP.y));
        asm("fma.rn.f32x2 %0, %1, %2, %3;" : "=l"(dA) : "l"(Ha1.y), "l"(R1A), "l"(dA));
        asm("fma.rn.f32x2 %0, %1, %2, %3;" : "=l"(dB) : "l"(Ha1.y), "l"(R1B), "l"(dB));
        asm("mul.rn.f32x2 %0, %1, %2;" : "=l"(accA[2*jp+1]) : "l"(accA[2*jp+1]), "l"(dA));
        asm("mul.rn.f32x2 %0, %1, %2;" : "=l"(accB[2*jp+1]) : "l"(accB[2*jp+1]), "l"(dB));
    }
}

// ---------------------------------------------------------------------------
// Main: warp quad g=wid>>2 covers words [g*64, g*64+64); quarter = wid&3
// handles head pairs quarter*8..quarter*8+7. Thread words: lane, lane+32.
// ---------------------------------------------------------------------------
__global__ void __launch_bounds__(THREADS, 1)
main_kernel(const float* __restrict__ pauli,
            const float* __restrict__ coeff,
            float* __restrict__ out,
            int N, int nblocks) {
    extern __shared__ float smem[];
    float*  sh_ha   = smem;
    float*  sh_hcp  = smem + OFF_HCP;
    float*  sh_hr   = smem + OFF_HR;
    float*  sh_part = smem + OFF_PART;
    float*  sh_p2   = smem + OFF_P2;
    double* sh_red  = (double*)(smem + OFF_RED);
    float*  sh_t    = smem + OFF_T;

    const int tid  = threadIdx.x;
    const int wid  = tid >> 5;
    const int lane = tid & 31;

    // Stage heads tables
    {
        const float4* src = (const float4*)g_ha;
        float4*       dst = (float4*)sh_ha;
        #pragma unroll
        for (int i = tid; i < HA_TOTAL / 4; i += THREADS) dst[i] = src[i];
        const float4* src2 = (const float4*)g_hcp;
        float4*       dst2 = (float4*)sh_hcp;
        #pragma unroll
        for (int i = tid; i < HCP_TOTAL / 4; i += THREADS) dst2[i] = src2[i];
    }
    if (tid < SS) sh_hr[tid] = g_hr[tid];

    // Stage pauli tile: float2 coalesced reads, padded-row float2 scatter
    const int base  = blockIdx.x * WORDS;
    const int valid = min(WORDS, N - base);
    const float2* gsrc2 = (const float2*)(pauli + (size_t)base * (SQ * SP));
    for (int i = tid; i < valid * 75; i += THREADS) {
        int w = i / 75;
        int k = i - w * 75;
        *(float2*)(sh_t + w * TROW + 2 * k) = gsrc2[i];
    }
    __syncthreads();

    // r-phase: in-place t -> (r0, r1, t2c); p2 products per (word, half).
    // 2 threads per word: half0 = q-pairs [0,13) (q0..25), half1 = [13,25).
    {
        int w    = tid >> 1;
        int half = tid & 1;
        if (w < valid) {
            float* row = sh_t + w * TROW;
            int p0 = half ? 13 : 0;
            int p1 = half ? 25 : 13;
            float pp = 1.0f;
            #pragma unroll 13
            for (int p = p0; p < p1; p++) {
                float2 v0 = *(float2*)(row + 6 * p);      // t0(q0), t1(q0)
                float2 v1 = *(float2*)(row + 6 * p + 2);  // t2(q0), t0(q1)
                float2 v2 = *(float2*)(row + 6 * p + 4);  // t1(q1), t2(q1)
                float t2c0 = fmaxf(v1.x, 1e-12f);
                float t2c1 = fmaxf(v2.y, 1e-12f);
                float rc0, rc1;
                asm("rcp.approx.f32 %0, %1;" : "=f"(rc0) : "f"(t2c0));
                asm("rcp.approx.f32 %0, %1;" : "=f"(rc1) : "f"(t2c1));
                float r00 = v0.x * rc0, r10 = v0.y * rc0;
                float r01 = v1.y * rc1, r11 = v2.x * rc1;
                pp *= t2c0;
                pp *= t2c1;
                *(float2*)(row + 6 * p)     = make_float2(r00,  r10);
                *(float2*)(row + 6 * p + 2) = make_float2(t2c0, r01);
                *(float2*)(row + 6 * p + 4) = make_float2(r11,  t2c1);
            }
            sh_p2[half * WORDS + w] = pp;
        }
    }
    __syncthreads();

    const int quarter = wid & 3;
    const int group   = wid >> 2;
    const int wA = group * 64 + lane;
    const int wB = wA + 32;
    const float* trowA = sh_t + wA * TROW;
    const float* trowB = sh_t + wB * TROW;

    uint64_t accA[8], accB[8];
    #pragma unroll
    for (int j = 0; j < 8; j++) { accA[j] = 0x3F8000003F800000ull; accB[j] = accA[j]; }

    const ulonglong2* ha_q  = (const ulonglong2*)sh_ha  + quarter * 8;   // + q*32
    const ulonglong2* hcp_q = (const ulonglong2*)sh_hcp + quarter * 4;   // + q*16

    const float4* tvA = (const float4*)trowA;
    const float4* tvB = (const float4*)trowB;
    #pragma unroll 4
    for (int c = 0; c < 12; c++) {
        float4 A0 = tvA[3*c+0], A1 = tvA[3*c+1], A2 = tvA[3*c+2];
        float4 B0 = tvB[3*c+0], B1 = tvB[3*c+1], B2 = tvB[3*c+2];
        const int q = 4 * c;
        // layout per q: [3q]=r0, [3q+1]=r1, [3q+2]=t2c(unused here)
        proc_q2(A0.x, A0.y, B0.x, B0.y, ha_q + (q+0)*32, hcp_q + (q+0)*16, accA, accB);
        proc_q2(A0.w, A1.x, B0.w, B1.x, ha_q + (q+1)*32, hcp_q + (q+1)*16, accA, accB);
        proc_q2(A1.z, A1.w, B1.z, B1.w, ha_q + (q+2)*32, hcp_q + (q+2)*16, accA, accB);
        proc_q2(A2.y, A2.z, B2.y, B2.z, ha_q + (q+3)*32, hcp_q + (q+3)*16, accA, accB);
    }
    {   // q = 48, 49 (floats 144..149, 8B-aligned)
        const float2* a2 = (const float2*)(trowA + 144);
        const float2* b2 = (const float2*)(trowB + 144);
        float2 ua = a2[0], va = a2[1], wa2 = a2[2];
        float2 ub = b2[0], vb = b2[1], wb2 = b2[2];
        proc_q2(ua.x, ua.y, ub.x, ub.y, ha_q + 48*32, hcp_q + 48*16, accA, accB);
        proc_q2(va.y, wa2.x, vb.y, wb2.x, ha_q + 49*32, hcp_q + 49*16, accA, accB);
    }

    // hr-weighted sums over this quarter's 16 heads
    float partA = 0.0f, partB = 0.0f;
    const float* hrq = sh_hr + quarter * 16;
    #pragma unroll
    for (int j = 0; j < 8; j++) {
        float lo, hi;
        asm("mov.b64 {%0, %1}, %2;" : "=f"(lo), "=f"(hi) : "l"(accA[j]));
        partA = fmaf(hrq[2 * j], lo, partA);
        partA = fmaf(hrq[2 * j + 1], hi, partA);
        asm("mov.b64 {%0, %1}, %2;" : "=f"(lo), "=f"(hi) : "l"(accB[j]));
        partB = fmaf(hrq[2 * j], lo, partB);
        partB = fmaf(hrq[2 * j + 1], hi, partB);
    }

    if (quarter != 0) {
        sh_part[(quarter - 1) * WORDS + wA] = partA;
        sh_part[(quarter - 1) * WORDS + wB] = partB;
    }
    __syncthreads();

    double v = 0.0;
    if (quarter == 0) {
        int nA = base + wA;
        if (nA < N) {
            float covf = partA + sh_part[wA] + sh_part[WORDS + wA] + sh_part[2 * WORDS + wA];
            double cov = (double)covf * (double)sh_p2[wA] * (double)sh_p2[WORDS + wA];
            float c = coeff[nA];
            v = (double)(c * c) / cov;
        }
        int nB = base + wB;
        if (nB < N) {
            float covf = partB + sh_part[wB] + sh_part[WORDS + wB] + sh_part[2 * WORDS + wB];
            double cov = (double)covf * (double)sh_p2[wB] * (double)sh_p2[WORDS + wB];
            float c = coeff[nB];
            v += (double)(c * c) / cov;
        }
        #pragma unroll
        for (int off = 16; off; off >>= 1)
            v += __shfl_down_sync(0xFFFFFFFFu, v, off);
        if (lane == 0) sh_red[group] = v;
    }
    __syncthreads();
    if (tid == 0) {
        double s = 0.0;
        #pragma unroll
        for (int w = 0; w < 4; w++) s += sh_red[w];
        atomicAdd(&g_accum, s);
        __threadfence();
        unsigned int ticket = atomicAdd(&g_count, 1u);
        if (ticket == (unsigned int)(nblocks - 1)) {
            out[0] = (float)g_accum;
        }
    }
}

// ---------------------------------------------------------------------------
extern "C" void kernel_launch(void* const* d_in, const int* in_sizes, int n_in,
                              void* d_out, int out_size) {
    const float* pauli = (const float*)d_in[0];   // [N, 50, 3] f32
    const float* coeff = (const float*)d_in[1];   // [N] f32
    const float* heads = (const float*)d_in[2];   // [64, 50, 3] f32
    const float* hr    = (const float*)d_in[3];   // [64] f32
    const int N = in_sizes[1];

    const size_t smem = (size_t)SMEM_FLOATS * sizeof(float);   // 203584 B
    cudaFuncSetAttribute(main_kernel, cudaFuncAttributeMaxDynamicSharedMemorySize, (int)smem);

    prep_kernel<<<50, 128>>>(heads, hr);
    const int grid = (N + WORDS - 1) / WORDS;
    main_kernel<<<grid, THREADS, smem>>>(pauli, coeff, (float*)d_out, N, grid);
}